// round 7
// baseline (speedup 1.0000x reference)
#include <cuda_runtime.h>
#include <cuda_fp16.h>
#include <math.h>

#define NLV 16
#define NDENSE 8
#define NHASH 8
#define TSZ (1u << 19)
#define TMASK (TSZ - 1u)
#define P1 2654435761u
#define P2 805459861u
#define P3 3674653429u
#define FSCALE 256.0f
#define INV_FSCALE (1.0f / 256.0f)

// Dense yz-quad grids, x-fastest, fp16x4 per 16B cell. Levels 0..7: ~5.85M cells.
#define DENSE_CAP 6000000
__device__ uint4 g_dense[DENSE_CAP];           // 96 MB
__device__ unsigned g_htab[NHASH << 19];       // fp16x2 copies of tables 8..15 (16 MB)

struct LvlParams {
    int res[NLV];
    int dofs[NDENSE];    // cell offset per dense level
    int soff[NDENSE];    // staging thread offset per dense level
};

__device__ __forceinline__ unsigned h2u(half2 h) { return *reinterpret_cast<unsigned*>(&h); }
__device__ __forceinline__ float2 u2f(unsigned u) {
    half2 h = *reinterpret_cast<half2*>(&u);
    return __half22float2(h);
}

// ---------------------------------------------------------------------------
// Merged staging kernel.
//  i <  htot           : fp16 conversion of hashed tables 8..15 (4 entries/thread)
//  i >= htot           : dense grid build, 4x4 yz cell blocks (25 gathers -> 16 cells)
// ---------------------------------------------------------------------------
__global__ void __launch_bounds__(256) stage_kernel(
    const float2* __restrict__ tables, LvlParams lp, int htot, int total)
{
    int i = blockIdx.x * 256 + threadIdx.x;
    if (i >= total) return;

    if (i < htot) {
        // --- hashed table fp16 conversion, 4 entries per thread ---
        int e = i * 4;
        const float4* src = reinterpret_cast<const float4*>(tables + ((size_t)8 << 19));
        float4 v01 = __ldg(src + i * 2);
        float4 v23 = __ldg(src + i * 2 + 1);
        uint4 q;
        q.x = h2u(__floats2half2_rn(v01.x * FSCALE, v01.y * FSCALE));
        q.y = h2u(__floats2half2_rn(v01.z * FSCALE, v01.w * FSCALE));
        q.z = h2u(__floats2half2_rn(v23.x * FSCALE, v23.y * FSCALE));
        q.w = h2u(__floats2half2_rn(v23.z * FSCALE, v23.w * FSCALE));
        *reinterpret_cast<uint4*>(g_htab + e) = q;
        return;
    }

    // --- dense staging: thread = (level, x, 4x4 yz cell block) ---
    int j = i - htot;
    int l = 0;
    #pragma unroll
    for (int k = 1; k < NDENSE; ++k)
        if (j >= lp.soff[k]) l = k;
    int r = lp.res[l];
    int rm = r - 1;
    int nz4 = (r + 3) >> 2;
    int rel = j - lp.soff[l];
    int x = rel % r;
    int t = rel / r;
    int zb = t % nz4;
    int yb = t / nz4;
    int y0 = yb * 4, z0 = zb * 4;

    unsigned hx = (unsigned)x * P1;
    const float2* tab = tables + (size_t)l * TSZ;

    unsigned vq[5][5];
    #pragma unroll
    for (int a = 0; a < 5; ++a) {
        int yv = min(y0 + a, rm);
        unsigned hy = (unsigned)yv * P2;
        #pragma unroll
        for (int c = 0; c < 5; ++c) {
            int zv = min(z0 + c, rm);
            float2 v = __ldg(tab + ((hx ^ hy ^ ((unsigned)zv * P3)) & TMASK));
            vq[a][c] = h2u(__floats2half2_rn(v.x * FSCALE, v.y * FSCALE));
        }
    }

    #pragma unroll
    for (int a = 0; a < 4; ++a) {
        int y = y0 + a;
        if (y >= r) break;
        #pragma unroll
        for (int c = 0; c < 4; ++c) {
            int z = z0 + c;
            if (z >= r) continue;
            uint4 q;
            q.x = vq[a][c];
            q.y = vq[a][c + 1];
            q.z = vq[a + 1][c];
            q.w = vq[a + 1][c + 1];
            g_dense[lp.dofs[l] + (y * r + z) * r + x] = q;
        }
    }
}

// ---------------------------------------------------------------------------
// Main kernel. Warp = 2 points (16 lanes each). hl = lane&15, k = hl>>1, sub = hl&1.
// Positions loaded by 6 lanes, broadcast via shuffle.
// Phase A: dense level k   -- lane pair loads adjacent x-cells (shared line ~7/8).
// Phase B: hashed level 8+k -- each lane 4 x-face gathers (.cg, L2-only).
// ---------------------------------------------------------------------------
__global__ void __launch_bounds__(256) hash_enc_main_kernel(
    const float* __restrict__ pos,
    float2* __restrict__ out,
    int npts, LvlParams lp)
{
    int tid = blockIdx.x * 256 + threadIdx.x;
    int lane = threadIdx.x & 31;
    int warp_p0 = (tid >> 5) * 2;                 // first point of this warp

    // cooperative position load: lanes 0..5 fetch 6 floats for 2 points
    float v = 0.0f;
    if (lane < 6) {
        size_t idx = (size_t)warp_p0 * 3 + lane;
        if (idx < (size_t)npts * 3) v = __ldcs(pos + idx);
    }
    int half = lane >> 4;                          // 0 or 1
    float px = __shfl_sync(0xFFFFFFFFu, v, half * 3 + 0);
    float py = __shfl_sync(0xFFFFFFFFu, v, half * 3 + 1);
    float pz = __shfl_sync(0xFFFFFFFFu, v, half * 3 + 2);

    int p = warp_p0 + half;
    if (p >= npts) return;
    int hl = lane & 15;
    int k = hl >> 1;
    int sub = hl & 1;

    // ---------- phase A addresses (dense level k) ----------
    int rA = lp.res[k];
    int rmA = rA - 1;
    float frA = (float)rmA;
    float sxA = px * frA, syA = py * frA, szA = pz * frA;
    float fxA = floorf(sxA), fyA = floorf(syA), fzA = floorf(szA);
    float wxA = sxA - fxA, wyA = syA - fyA, wzA = szA - fzA;
    int x0A = min(max((int)fxA, 0), rmA);
    int y0A = min(max((int)fyA, 0), rmA);
    int z0A = min(max((int)fzA, 0), rmA);
    int xsA = min(x0A + sub, rmA);
    const uint4* gA = g_dense + lp.dofs[k];
    uint4 q = __ldg(gA + ((y0A * rA + z0A) * rA + xsA));

    // ---------- phase B addresses (hashed level 8+k) ----------
    int lB = 8 + k;
    int rB = lp.res[lB];
    int rmB = rB - 1;
    float frB = (float)rmB;
    float sxB = px * frB, syB = py * frB, szB = pz * frB;
    float fxB = floorf(sxB), fyB = floorf(syB), fzB = floorf(szB);
    float wxB = sxB - fxB, wyB = syB - fyB, wzB = szB - fzB;
    int x0B = min(max((int)fxB, 0), rmB);
    int y0B = min(max((int)fyB, 0), rmB);
    int z0B = min(max((int)fzB, 0), rmB);
    int xsB = min(x0B + sub, rmB);
    unsigned hxB = (unsigned)xsB * P1;
    unsigned hy0 = (unsigned)y0B * P2, hy1 = (unsigned)min(y0B + 1, rmB) * P2;
    unsigned hz0 = (unsigned)z0B * P3, hz1 = (unsigned)min(z0B + 1, rmB) * P3;
    const unsigned* ht = g_htab + ((size_t)k << 19);
    unsigned c00u = __ldcg(ht + ((hxB ^ hy0 ^ hz0) & TMASK));
    unsigned c01u = __ldcg(ht + ((hxB ^ hy0 ^ hz1) & TMASK));
    unsigned c10u = __ldcg(ht + ((hxB ^ hy1 ^ hz0) & TMASK));
    unsigned c11u = __ldcg(ht + ((hxB ^ hy1 ^ hz1) & TMASK));

    // ---------- phase A math ----------
    float2 a00 = u2f(q.x), a01 = u2f(q.y), a10 = u2f(q.z), a11 = u2f(q.w);
    float wxfA = (sub ? wxA : 1.0f - wxA) * INV_FSCALE;
    float uyA = 1.0f - wyA, uzA = 1.0f - wzA;
    float wA00 = wxfA * uyA * uzA, wA01 = wxfA * uyA * wzA;
    float wA10 = wxfA * wyA * uzA, wA11 = wxfA * wyA * wzA;
    float fA0 = a00.x * wA00, fA1 = a00.y * wA00;
    fA0 = fmaf(a01.x, wA01, fA0);  fA1 = fmaf(a01.y, wA01, fA1);
    fA0 = fmaf(a10.x, wA10, fA0);  fA1 = fmaf(a10.y, wA10, fA1);
    fA0 = fmaf(a11.x, wA11, fA0);  fA1 = fmaf(a11.y, wA11, fA1);
    fA0 += __shfl_xor_sync(0xFFFFFFFFu, fA0, 1);
    fA1 += __shfl_xor_sync(0xFFFFFFFFu, fA1, 1);

    // ---------- phase B math ----------
    float2 c00 = u2f(c00u), c01 = u2f(c01u), c10 = u2f(c10u), c11 = u2f(c11u);
    float wxfB = (sub ? wxB : 1.0f - wxB) * INV_FSCALE;
    float uyB = 1.0f - wyB, uzB = 1.0f - wzB;
    float wB00 = wxfB * uyB * uzB, wB01 = wxfB * uyB * wzB;
    float wB10 = wxfB * wyB * uzB, wB11 = wxfB * wyB * wzB;
    float fB0 = c00.x * wB00, fB1 = c00.y * wB00;
    fB0 = fmaf(c01.x, wB01, fB0);  fB1 = fmaf(c01.y, wB01, fB1);
    fB0 = fmaf(c10.x, wB10, fB0);  fB1 = fmaf(c10.y, wB10, fB1);
    fB0 = fmaf(c11.x, wB11, fB0);  fB1 = fmaf(c11.y, wB11, fB1);
    fB0 += __shfl_xor_sync(0xFFFFFFFFu, fB0, 1);
    fB1 += __shfl_xor_sync(0xFFFFFFFFu, fB1, 1);

    // ---------- store ----------
    int lvl = sub ? lB : k;
    float2 o;
    o.x = sub ? fB0 : fA0;
    o.y = sub ? fB1 : fA1;
    __stcs(out + (size_t)p * 16 + lvl, o);
}

// ---------------------------------------------------------------------------
extern "C" void kernel_launch(void* const* d_in, const int* in_sizes, int n_in,
                              void* d_out, int out_size)
{
    const float*  pos    = (const float*)d_in[0];
    const float2* tables = (const float2*)d_in[1];
    int npts = in_sizes[0] / 3;

    LvlParams lp;
    double b = exp((log(2048.0) - log(16.0)) / 15.0);
    for (int l = 0; l < NLV; ++l) {
        double r = 16.0 * pow(b, (double)l);
        int ri = (int)r;
        if (ri > 2048) ri = 2048;
        lp.res[l] = ri;
    }

    // dense level cell offsets + staging thread offsets (4x4 yz blocks)
    int dtot = 0, stot = 0;
    for (int l = 0; l < NDENSE; ++l) {
        int r = lp.res[l];
        lp.dofs[l] = dtot;
        lp.soff[l] = stot;
        dtot += r * r * r;
        int n4 = (r + 3) / 4;
        stot += r * n4 * n4;
    }

    int htot = (NHASH << 19) / 4;       // 4 entries per thread
    int total = htot + stot;
    stage_kernel<<<(total + 255) / 256, 256>>>(tables, lp, htot, total);

    long nthreads = (long)((npts + 1) / 2) * 32;   // 2 points per warp
    int blocks = (int)((nthreads + 255) / 256);
    hash_enc_main_kernel<<<blocks, 256>>>(pos, (float2*)d_out, npts, lp);
}

// round 8
// speedup vs baseline: 1.1062x; 1.1062x over previous
#include <cuda_runtime.h>
#include <cuda_fp16.h>
#include <math.h>

#define NLV 16
#define NDENSE 8
#define NHASH 8
#define TSZ (1u << 19)
#define TMASK (TSZ - 1u)
#define P1 2654435761u
#define P2 805459861u
#define P3 3674653429u
#define FSCALE 256.0f
#define INV_FSCALE (1.0f / 256.0f)

// Dense yz-quad grids, x-fastest, fp16x4 per 16B cell. Levels 0..7: ~5.85M cells.
#define DENSE_CAP 6000000
__device__ uint4 g_dense[DENSE_CAP];           // 96 MB
__device__ unsigned g_htab[NHASH << 19];       // fp16x2 copies of tables 8..15 (16 MB)

struct LvlParams {
    int res[NLV];
    int dofs[NDENSE];    // cell offset per dense level
    int soff[NDENSE];    // staging thread offset per dense level
};

__device__ __forceinline__ unsigned h2u(half2 h) { return *reinterpret_cast<unsigned*>(&h); }
__device__ __forceinline__ float2 u2f(unsigned u) {
    half2 h = *reinterpret_cast<half2*>(&u);
    return __half22float2(h);
}

// ---------------------------------------------------------------------------
// fp16 copies of hashed tables (levels 8..15), vectorized: 4 entries/thread.
// ---------------------------------------------------------------------------
__global__ void __launch_bounds__(256) stage_htab_kernel(const float2* __restrict__ tables)
{
    int i = blockIdx.x * 256 + threadIdx.x;
    if (i >= (NHASH << 19) / 4) return;
    const float4* src = reinterpret_cast<const float4*>(tables + ((size_t)8 << 19));
    float4 v01 = __ldg(src + (size_t)i * 2);
    float4 v23 = __ldg(src + (size_t)i * 2 + 1);
    uint4 q;
    q.x = h2u(__floats2half2_rn(v01.x * FSCALE, v01.y * FSCALE));
    q.y = h2u(__floats2half2_rn(v01.z * FSCALE, v01.w * FSCALE));
    q.z = h2u(__floats2half2_rn(v23.x * FSCALE, v23.y * FSCALE));
    q.w = h2u(__floats2half2_rn(v23.z * FSCALE, v23.w * FSCALE));
    *reinterpret_cast<uint4*>(g_htab + (size_t)i * 4) = q;
}

// ---------------------------------------------------------------------------
// Dense staging: thread = (level, x, 2x2 yz cell block). 9 vertex gathers -> 4 cells.
// Cell layout: idx = dofs[l] + (y*r + z)*r + x  (x fastest for lane-pair coalescing)
// Cell quad: q.x=(y0,z0) q.y=(y0,z1) q.z=(y1,z0) q.w=(y1,z1)
// ---------------------------------------------------------------------------
__global__ void __launch_bounds__(256) stage_dense_kernel(
    const float2* __restrict__ tables, LvlParams lp, int total)
{
    int i = blockIdx.x * 256 + threadIdx.x;
    if (i >= total) return;

    int l = 0;
    #pragma unroll
    for (int k = 1; k < NDENSE; ++k)
        if (i >= lp.soff[k]) l = k;
    int r = lp.res[l];
    int rm = r - 1;
    int nz2 = (r + 1) >> 1;
    int rel = i - lp.soff[l];
    int x = rel % r;
    int t = rel / r;
    int zb = t % nz2;
    int yb = t / nz2;
    int y0 = yb * 2, z0 = zb * 2;

    unsigned hx = (unsigned)x * P1;
    const float2* tab = tables + (size_t)l * TSZ;

    unsigned vq[3][3];
    #pragma unroll
    for (int a = 0; a < 3; ++a) {
        int yv = min(y0 + a, rm);
        unsigned hy = (unsigned)yv * P2;
        #pragma unroll
        for (int c = 0; c < 3; ++c) {
            int zv = min(z0 + c, rm);
            float2 v = __ldg(tab + ((hx ^ hy ^ ((unsigned)zv * P3)) & TMASK));
            vq[a][c] = h2u(__floats2half2_rn(v.x * FSCALE, v.y * FSCALE));
        }
    }

    #pragma unroll
    for (int a = 0; a < 2; ++a) {
        int y = y0 + a;
        if (y >= r) break;
        #pragma unroll
        for (int c = 0; c < 2; ++c) {
            int z = z0 + c;
            if (z >= r) continue;
            uint4 q;
            q.x = vq[a][c];
            q.y = vq[a][c + 1];
            q.z = vq[a + 1][c];
            q.w = vq[a + 1][c + 1];
            g_dense[lp.dofs[l] + (y * r + z) * r + x] = q;
        }
    }
}

// ---------------------------------------------------------------------------
// Main kernel. 16 lanes per point. hl = lane&15, pair k = hl>>1, sub = hl&1.
// Phase A: dense level k    -- lane pair loads adjacent x-cells (shared line ~7/8).
// Phase B: hashed level 8+k -- each lane handles its x-face (4 gathers).
// Positions in [0,1) => floor coords in [0, rm-1], +1 <= rm: NO clamps needed.
// ---------------------------------------------------------------------------
__global__ void __launch_bounds__(256) hash_enc_main_kernel(
    const float* __restrict__ pos,
    float2* __restrict__ out,
    int npts, LvlParams lp)
{
    int tid = blockIdx.x * 256 + threadIdx.x;
    int p = tid >> 4;
    if (p >= npts) return;
    int hl = tid & 15;
    int k = hl >> 1;
    int sub = hl & 1;

    float px = __ldg(pos + 3 * (size_t)p + 0);
    float py = __ldg(pos + 3 * (size_t)p + 1);
    float pz = __ldg(pos + 3 * (size_t)p + 2);

    // ---------- phase A addresses (dense level k) ----------
    int rA = lp.res[k];
    float frA = (float)(rA - 1);
    float sxA = px * frA, syA = py * frA, szA = pz * frA;
    float fxA = floorf(sxA), fyA = floorf(syA), fzA = floorf(szA);
    float wxA = sxA - fxA, wyA = syA - fyA, wzA = szA - fzA;
    int x0A = (int)fxA, y0A = (int)fyA, z0A = (int)fzA;
    int xsA = x0A + sub;
    const uint4* gA = g_dense + lp.dofs[k];
    uint4 q = __ldg(gA + ((y0A * rA + z0A) * rA + xsA));

    // ---------- phase B addresses (hashed level 8+k) ----------
    int rB = lp.res[8 + k];
    float frB = (float)(rB - 1);
    float sxB = px * frB, syB = py * frB, szB = pz * frB;
    float fxB = floorf(sxB), fyB = floorf(syB), fzB = floorf(szB);
    float wxB = sxB - fxB, wyB = syB - fyB, wzB = szB - fzB;
    int x0B = (int)fxB, y0B = (int)fyB, z0B = (int)fzB;
    unsigned hxB = (unsigned)(x0B + sub) * P1;
    unsigned hy0 = (unsigned)y0B * P2, hy1 = hy0 + P2;
    unsigned hz0 = (unsigned)z0B * P3, hz1 = hz0 + P3;
    const unsigned* ht = g_htab + ((size_t)k << 19);
    unsigned c00u = __ldg(ht + ((hxB ^ hy0 ^ hz0) & TMASK));
    unsigned c01u = __ldg(ht + ((hxB ^ hy0 ^ hz1) & TMASK));
    unsigned c10u = __ldg(ht + ((hxB ^ hy1 ^ hz0) & TMASK));
    unsigned c11u = __ldg(ht + ((hxB ^ hy1 ^ hz1) & TMASK));

    // ---------- phase A math ----------
    float2 a00 = u2f(q.x), a01 = u2f(q.y), a10 = u2f(q.z), a11 = u2f(q.w);
    float wxfA = (sub ? wxA : 1.0f - wxA) * INV_FSCALE;
    float uyA = 1.0f - wyA, uzA = 1.0f - wzA;
    float wA00 = wxfA * uyA * uzA, wA01 = wxfA * uyA * wzA;
    float wA10 = wxfA * wyA * uzA, wA11 = wxfA * wyA * wzA;
    float fA0 = a00.x * wA00, fA1 = a00.y * wA00;
    fA0 = fmaf(a01.x, wA01, fA0);  fA1 = fmaf(a01.y, wA01, fA1);
    fA0 = fmaf(a10.x, wA10, fA0);  fA1 = fmaf(a10.y, wA10, fA1);
    fA0 = fmaf(a11.x, wA11, fA0);  fA1 = fmaf(a11.y, wA11, fA1);
    fA0 += __shfl_xor_sync(0xFFFFFFFFu, fA0, 1);
    fA1 += __shfl_xor_sync(0xFFFFFFFFu, fA1, 1);

    // ---------- phase B math ----------
    float2 c00 = u2f(c00u), c01 = u2f(c01u), c10 = u2f(c10u), c11 = u2f(c11u);
    float wxfB = (sub ? wxB : 1.0f - wxB) * INV_FSCALE;
    float uyB = 1.0f - wyB, uzB = 1.0f - wzB;
    float wB00 = wxfB * uyB * uzB, wB01 = wxfB * uyB * wzB;
    float wB10 = wxfB * wyB * uzB, wB11 = wxfB * wyB * wzB;
    float fB0 = c00.x * wB00, fB1 = c00.y * wB00;
    fB0 = fmaf(c01.x, wB01, fB0);  fB1 = fmaf(c01.y, wB01, fB1);
    fB0 = fmaf(c10.x, wB10, fB0);  fB1 = fmaf(c10.y, wB10, fB1);
    fB0 = fmaf(c11.x, wB11, fB0);  fB1 = fmaf(c11.y, wB11, fB1);
    fB0 += __shfl_xor_sync(0xFFFFFFFFu, fB0, 1);
    fB1 += __shfl_xor_sync(0xFFFFFFFFu, fB1, 1);

    // ---------- store ----------
    int lvl = sub ? (8 + k) : k;
    float2 o;
    o.x = sub ? fB0 : fA0;
    o.y = sub ? fB1 : fA1;
    __stcs(out + (size_t)p * 16 + lvl, o);
}

// ---------------------------------------------------------------------------
extern "C" void kernel_launch(void* const* d_in, const int* in_sizes, int n_in,
                              void* d_out, int out_size)
{
    const float*  pos    = (const float*)d_in[0];
    const float2* tables = (const float2*)d_in[1];
    int npts = in_sizes[0] / 3;

    LvlParams lp;
    double b = exp((log(2048.0) - log(16.0)) / 15.0);
    for (int l = 0; l < NLV; ++l) {
        double r = 16.0 * pow(b, (double)l);
        int ri = (int)r;
        if (ri > 2048) ri = 2048;
        lp.res[l] = ri;
    }

    // dense level cell offsets + staging thread offsets (2x2 yz blocks)
    int dtot = 0, stot = 0;
    for (int l = 0; l < NDENSE; ++l) {
        int r = lp.res[l];
        lp.dofs[l] = dtot;
        lp.soff[l] = stot;
        dtot += r * r * r;
        int n2 = (r + 1) / 2;
        stot += r * n2 * n2;
    }

    stage_htab_kernel<<<(((NHASH << 19) / 4) + 255) / 256, 256>>>(tables);
    stage_dense_kernel<<<(stot + 255) / 256, 256>>>(tables, lp, stot);

    long total = (long)npts * 16;
    int blocks = (int)((total + 255) / 256);
    hash_enc_main_kernel<<<blocks, 256>>>(pos, (float2*)d_out, npts, lp);
}